// round 2
// baseline (speedup 1.0000x reference)
#include <cuda_runtime.h>

#define HIDDEN 2048
#define HEADS 16
#define HEAD_DIM 128
#define BATCH 2
#define SEQ 2048
#define MROWS (BATCH * SEQ)  // 4096

// ---------------- scratch (no allocations allowed) ----------------
__device__ float g_q[MROWS * HIDDEN];     // 32 MB
__device__ float g_k[MROWS * HEAD_DIM];   // 2 MB
__device__ float g_v[MROWS * HEAD_DIM];   // 2 MB
__device__ float g_att[MROWS * HIDDEN];   // 32 MB

// ---------------- GEMM: C[M,N] = A[M,K] @ B[N,K]^T ----------------
// 128x128 tile, BK=16, 256 threads, 8x8 microtile.
__global__ void __launch_bounds__(256) gemm_abt(const float* __restrict__ A,
                                                const float* __restrict__ B,
                                                float* __restrict__ C,
                                                int M, int N, int K) {
    __shared__ float As[16][128];
    __shared__ float Bs[16][128];

    const int tid = threadIdx.x;
    const int tx = tid & 15;       // 0..15
    const int ty = tid >> 4;       // 0..15
    const int m0 = blockIdx.y * 128;
    const int n0 = blockIdx.x * 128;

    float acc[8][8];
#pragma unroll
    for (int i = 0; i < 8; i++)
#pragma unroll
        for (int j = 0; j < 8; j++) acc[i][j] = 0.0f;

    for (int k0 = 0; k0 < K; k0 += 16) {
        // stage 128x16 of A and B (transposed into [k][row])
#pragma unroll
        for (int li = 0; li < 2; li++) {
            int f  = tid + li * 256;      // float4 index 0..511
            int r  = f >> 2;              // row in tile 0..127
            int kc = (f & 3) * 4;         // k offset 0,4,8,12
            float4 av = *(const float4*)(A + (size_t)(m0 + r) * K + k0 + kc);
            As[kc + 0][r] = av.x;
            As[kc + 1][r] = av.y;
            As[kc + 2][r] = av.z;
            As[kc + 3][r] = av.w;
            float4 bv = *(const float4*)(B + (size_t)(n0 + r) * K + k0 + kc);
            Bs[kc + 0][r] = bv.x;
            Bs[kc + 1][r] = bv.y;
            Bs[kc + 2][r] = bv.z;
            Bs[kc + 3][r] = bv.w;
        }
        __syncthreads();

#pragma unroll
        for (int kk = 0; kk < 16; kk++) {
            float ar[8], br[8];
            float4 a0 = *(const float4*)&As[kk][ty * 8];
            float4 a1 = *(const float4*)&As[kk][ty * 8 + 4];
            float4 b0 = *(const float4*)&Bs[kk][tx * 8];
            float4 b1 = *(const float4*)&Bs[kk][tx * 8 + 4];
            ar[0] = a0.x; ar[1] = a0.y; ar[2] = a0.z; ar[3] = a0.w;
            ar[4] = a1.x; ar[5] = a1.y; ar[6] = a1.z; ar[7] = a1.w;
            br[0] = b0.x; br[1] = b0.y; br[2] = b0.z; br[3] = b0.w;
            br[4] = b1.x; br[5] = b1.y; br[6] = b1.z; br[7] = b1.w;
#pragma unroll
            for (int i = 0; i < 8; i++)
#pragma unroll
                for (int j = 0; j < 8; j++)
                    acc[i][j] = fmaf(ar[i], br[j], acc[i][j]);
        }
        __syncthreads();
    }

#pragma unroll
    for (int i = 0; i < 8; i++) {
        float* crow = C + (size_t)(m0 + ty * 8 + i) * N + n0 + tx * 8;
        float4 c0, c1;
        c0.x = acc[i][0]; c0.y = acc[i][1]; c0.z = acc[i][2]; c0.w = acc[i][3];
        c1.x = acc[i][4]; c1.y = acc[i][5]; c1.z = acc[i][6]; c1.w = acc[i][7];
        *(float4*)crow = c0;
        *(float4*)(crow + 4) = c1;
    }
}

// ---------------- Flash attention (fp32, single shared KV head) ----------------
// Grid: (SEQ/64, HEADS, BATCH). 256 threads.
// Per CTA: 64 query rows of head h; loop key tiles of 64; online softmax.
#define KS_STRIDE 129  // pad to avoid bank conflicts on column-varying reads
#define SS_STRIDE 65

__global__ void __launch_bounds__(256) attn_kernel(const float* __restrict__ Q,
                                                   const float* __restrict__ Km,
                                                   const float* __restrict__ Vm,
                                                   float* __restrict__ O) {
    const int b = blockIdx.z;
    const int h = blockIdx.y;
    const int q0 = blockIdx.x * 64;

    extern __shared__ float sm[];
    float* qs  = sm;                       // [64][128]
    float* ks  = qs + 64 * 128;            // [64][129]
    float* vs  = ks + 64 * KS_STRIDE;      // [64][128]
    float* ss  = vs + 64 * 128;            // [64][65]
    float* m_s = ss + 64 * SS_STRIDE;      // [64]
    float* l_s = m_s + 64;                 // [64]
    float* f_s = l_s + 64;                 // [64]

    const int tid = threadIdx.x;
    const int tx = tid & 15;
    const int ty = tid >> 4;
    const int wid = tid >> 5;
    const int lane = tid & 31;
    const float inv_norm = 0.08838834764831845f;  // 1/sqrt(128)

    // load Q tile (64 x 128)
    for (int i = tid; i < 64 * 32; i += 256) {
        int r = i >> 5;
        int c4 = (i & 31) * 4;
        float4 v4 = *(const float4*)(Q + (size_t)(b * SEQ + q0 + r) * HIDDEN + h * HEAD_DIM + c4);
        *(float4*)(qs + r * 128 + c4) = v4;
    }
    if (tid < 64) {
        m_s[tid] = -3.0e38f;
        l_s[tid] = 0.0f;
    }
    __syncthreads();

    // PV accumulators: thread owns (row = tid>>2, 32 cols starting at (tid&3)*32)
    float accv[32];
#pragma unroll
    for (int i = 0; i < 32; i++) accv[i] = 0.0f;
    const int prow = tid >> 2;
    const int pcb = (tid & 3) * 32;

    for (int t0 = 0; t0 < SEQ; t0 += 64) {
        // load K, V tiles (64 x 128)
        for (int i = tid; i < 64 * 32; i += 256) {
            int r = i >> 5;
            int c4 = (i & 31) * 4;
            float4 kv = *(const float4*)(Km + (size_t)(b * SEQ + t0 + r) * HEAD_DIM + c4);
            ks[r * KS_STRIDE + c4 + 0] = kv.x;
            ks[r * KS_STRIDE + c4 + 1] = kv.y;
            ks[r * KS_STRIDE + c4 + 2] = kv.z;
            ks[r * KS_STRIDE + c4 + 3] = kv.w;
            float4 vv = *(const float4*)(Vm + (size_t)(b * SEQ + t0 + r) * HEAD_DIM + c4);
            *(float4*)(vs + r * 128 + c4) = vv;
        }
        __syncthreads();

        // scores: 64x64 tile; thread (ty,tx) computes 4x4
        float s[4][4];
#pragma unroll
        for (int i = 0; i < 4; i++)
#pragma unroll
            for (int j = 0; j < 4; j++) s[i][j] = 0.0f;

#pragma unroll 4
        for (int d = 0; d < 128; d++) {
            float a0 = qs[(ty * 4 + 0) * 128 + d];
            float a1 = qs[(ty * 4 + 1) * 128 + d];
            float a2 = qs[(ty * 4 + 2) * 128 + d];
            float a3 = qs[(ty * 4 + 3) * 128 + d];
            float b0 = ks[(tx * 4 + 0) * KS_STRIDE + d];
            float b1 = ks[(tx * 4 + 1) * KS_STRIDE + d];
            float b2 = ks[(tx * 4 + 2) * KS_STRIDE + d];
            float b3 = ks[(tx * 4 + 3) * KS_STRIDE + d];
            s[0][0] = fmaf(a0, b0, s[0][0]); s[0][1] = fmaf(a0, b1, s[0][1]);
            s[0][2] = fmaf(a0, b2, s[0][2]); s[0][3] = fmaf(a0, b3, s[0][3]);
            s[1][0] = fmaf(a1, b0, s[1][0]); s[1][1] = fmaf(a1, b1, s[1][1]);
            s[1][2] = fmaf(a1, b2, s[1][2]); s[1][3] = fmaf(a1, b3, s[1][3]);
            s[2][0] = fmaf(a2, b0, s[2][0]); s[2][1] = fmaf(a2, b1, s[2][1]);
            s[2][2] = fmaf(a2, b2, s[2][2]); s[2][3] = fmaf(a2, b3, s[2][3]);
            s[3][0] = fmaf(a3, b0, s[3][0]); s[3][1] = fmaf(a3, b1, s[3][1]);
            s[3][2] = fmaf(a3, b2, s[3][2]); s[3][3] = fmaf(a3, b3, s[3][3]);
        }
#pragma unroll
        for (int i = 0; i < 4; i++)
#pragma unroll
            for (int j = 0; j < 4; j++)
                ss[(ty * 4 + i) * SS_STRIDE + tx * 4 + j] = s[i][j] * inv_norm;
        __syncthreads();

        // online softmax: warp `wid` owns rows wid*8 .. wid*8+7
#pragma unroll
        for (int rr = 0; rr < 8; rr++) {
            int row = wid * 8 + rr;
            float v0 = ss[row * SS_STRIDE + lane];
            float v1 = ss[row * SS_STRIDE + 32 + lane];
            float mx = fmaxf(v0, v1);
#pragma unroll
            for (int off = 16; off > 0; off >>= 1)
                mx = fmaxf(mx, __shfl_xor_sync(0xffffffffu, mx, off));
            float m_old = m_s[row];
            float m_new = fmaxf(m_old, mx);
            float p0 = __expf(v0 - m_new);
            float p1 = __expf(v1 - m_new);
            ss[row * SS_STRIDE + lane] = p0;
            ss[row * SS_STRIDE + 32 + lane] = p1;
            float sum = p0 + p1;
#pragma unroll
            for (int off = 16; off > 0; off >>= 1)
                sum += __shfl_xor_sync(0xffffffffu, sum, off);
            if (lane == 0) {
                float f = __expf(m_old - m_new);
                l_s[row] = l_s[row] * f + sum;
                m_s[row] = m_new;
                f_s[row] = f;
            }
        }
        __syncthreads();

        // rescale accumulators and add P @ V
        float f = f_s[prow];
#pragma unroll
        for (int i = 0; i < 32; i++) accv[i] *= f;
#pragma unroll 4
        for (int j = 0; j < 64; j++) {
            float p = ss[prow * SS_STRIDE + j];
            const float4* vrow = (const float4*)(vs + j * 128 + pcb);
#pragma unroll
            for (int c4 = 0; c4 < 8; c4++) {
                float4 vv = vrow[c4];
                accv[c4 * 4 + 0] = fmaf(p, vv.x, accv[c4 * 4 + 0]);
                accv[c4 * 4 + 1] = fmaf(p, vv.y, accv[c4 * 4 + 1]);
                accv[c4 * 4 + 2] = fmaf(p, vv.z, accv[c4 * 4 + 2]);
                accv[c4 * 4 + 3] = fmaf(p, vv.w, accv[c4 * 4 + 3]);
            }
        }
        __syncthreads();
    }

    // epilogue
    float linv = 1.0f / l_s[prow];
    float* optr = O + (size_t)(b * SEQ + q0 + prow) * HIDDEN + h * HEAD_DIM + pcb;
#pragma unroll
    for (int c4 = 0; c4 < 8; c4++) {
        float4 o4;
        o4.x = accv[c4 * 4 + 0] * linv;
        o4.y = accv[c4 * 4 + 1] * linv;
        o4.z = accv[c4 * 4 + 2] * linv;
        o4.w = accv[c4 * 4 + 3] * linv;
        *(float4*)(optr + c4 * 4) = o4;
    }
}

// ---------------- launch ----------------
extern "C" void kernel_launch(void* const* d_in, const int* in_sizes, int n_in,
                              void* d_out, int out_size) {
    (void)in_sizes; (void)n_in; (void)out_size;
    const float* x  = (const float*)d_in[0];
    const float* wq = (const float*)d_in[1];
    const float* wk = (const float*)d_in[2];
    const float* wv = (const float*)d_in[3];
    const float* wo = (const float*)d_in[4];
    float* out = (float*)d_out;

    float *qb, *kb, *vb, *ab;
    cudaGetSymbolAddress((void**)&qb, g_q);
    cudaGetSymbolAddress((void**)&kb, g_k);
    cudaGetSymbolAddress((void**)&vb, g_v);
    cudaGetSymbolAddress((void**)&ab, g_att);

    const int smem_attn = (64 * 128 + 64 * KS_STRIDE + 64 * 128 + 64 * SS_STRIDE + 3 * 64)
                          * (int)sizeof(float);
    static int configured = 0;
    if (!configured) {
        cudaFuncSetAttribute(attn_kernel, cudaFuncAttributeMaxDynamicSharedMemorySize,
                             smem_attn);
        configured = 1;
    }

    dim3 blk(256);
    // Q projection: [4096,2048] = x @ wq^T
    gemm_abt<<<dim3(HIDDEN / 128, MROWS / 128), blk>>>(x, wq, qb, MROWS, HIDDEN, HIDDEN);
    // K projection: [4096,128]
    gemm_abt<<<dim3(HEAD_DIM / 128, MROWS / 128), blk>>>(x, wk, kb, MROWS, HEAD_DIM, HIDDEN);
    // V projection: [4096,128]
    gemm_abt<<<dim3(HEAD_DIM / 128, MROWS / 128), blk>>>(x, wv, vb, MROWS, HEAD_DIM, HIDDEN);
    // attention
    attn_kernel<<<dim3(SEQ / 64, HEADS, BATCH), blk, smem_attn>>>(qb, kb, vb, ab);
    // output projection
    gemm_abt<<<dim3(HIDDEN / 128, MROWS / 128), blk>>>(ab, wo, out, MROWS, HIDDEN, HIDDEN);
}

// round 3
// speedup vs baseline: 2.1653x; 2.1653x over previous
#include <cuda_runtime.h>

#define HIDDEN 2048
#define HEADS 16
#define HEAD_DIM 128
#define BATCH 2
#define SEQ 2048
#define MROWS (BATCH * SEQ)  // 4096

// ---------------- scratch (no allocations allowed) ----------------
__device__ float g_q[MROWS * HIDDEN];     // 32 MB
__device__ float g_k[MROWS * HEAD_DIM];   // 2 MB
__device__ float g_v[MROWS * HEAD_DIM];   // 2 MB
__device__ float g_att[MROWS * HIDDEN];   // 32 MB

// ---------------- GEMM: C[M,N] = A[M,K] @ B[N,K]^T ----------------
// 128x128 tile, BK=16, 256 threads, 8x8 microtile. (fp32 roofline-bound)
__global__ void __launch_bounds__(256) gemm_abt(const float* __restrict__ A,
                                                const float* __restrict__ B,
                                                float* __restrict__ C,
                                                int M, int N, int K) {
    __shared__ float As[16][128];
    __shared__ float Bs[16][128];

    const int tid = threadIdx.x;
    const int tx = tid & 15;
    const int ty = tid >> 4;
    const int m0 = blockIdx.y * 128;
    const int n0 = blockIdx.x * 128;

    float acc[8][8];
#pragma unroll
    for (int i = 0; i < 8; i++)
#pragma unroll
        for (int j = 0; j < 8; j++) acc[i][j] = 0.0f;

    for (int k0 = 0; k0 < K; k0 += 16) {
#pragma unroll
        for (int li = 0; li < 2; li++) {
            int f  = tid + li * 256;
            int r  = f >> 2;
            int kc = (f & 3) * 4;
            float4 av = *(const float4*)(A + (size_t)(m0 + r) * K + k0 + kc);
            As[kc + 0][r] = av.x;
            As[kc + 1][r] = av.y;
            As[kc + 2][r] = av.z;
            As[kc + 3][r] = av.w;
            float4 bv = *(const float4*)(B + (size_t)(n0 + r) * K + k0 + kc);
            Bs[kc + 0][r] = bv.x;
            Bs[kc + 1][r] = bv.y;
            Bs[kc + 2][r] = bv.z;
            Bs[kc + 3][r] = bv.w;
        }
        __syncthreads();

#pragma unroll
        for (int kk = 0; kk < 16; kk++) {
            float ar[8], br[8];
            float4 a0 = *(const float4*)&As[kk][ty * 8];
            float4 a1 = *(const float4*)&As[kk][ty * 8 + 4];
            float4 b0 = *(const float4*)&Bs[kk][tx * 8];
            float4 b1 = *(const float4*)&Bs[kk][tx * 8 + 4];
            ar[0] = a0.x; ar[1] = a0.y; ar[2] = a0.z; ar[3] = a0.w;
            ar[4] = a1.x; ar[5] = a1.y; ar[6] = a1.z; ar[7] = a1.w;
            br[0] = b0.x; br[1] = b0.y; br[2] = b0.z; br[3] = b0.w;
            br[4] = b1.x; br[5] = b1.y; br[6] = b1.z; br[7] = b1.w;
#pragma unroll
            for (int i = 0; i < 8; i++)
#pragma unroll
                for (int j = 0; j < 8; j++)
                    acc[i][j] = fmaf(ar[i], br[j], acc[i][j]);
        }
        __syncthreads();
    }

#pragma unroll
    for (int i = 0; i < 8; i++) {
        float* crow = C + (size_t)(m0 + ty * 8 + i) * N + n0 + tx * 8;
        float4 c0, c1;
        c0.x = acc[i][0]; c0.y = acc[i][1]; c0.z = acc[i][2]; c0.w = acc[i][3];
        c1.x = acc[i][4]; c1.y = acc[i][5]; c1.z = acc[i][6]; c1.w = acc[i][7];
        *(float4*)crow = c0;
        *(float4*)(crow + 4) = c1;
    }
}

// ---------------- Flash attention v2 (fp32, FMA-bound layout) ----------------
// Grid: (SEQ/64, HEADS, BATCH). 256 threads = 16x16 thread grid.
// Q,K stored TRANSPOSED in smem ([d][pos], stride 68) so both matmul stages
// use float4 LDS on the position axis:
//   QK: 4x4 microtile, 2 LDS.128 / 16 FMA
//   PV: 4x8 microtile, 4 bcast LDS.32 + 2 LDS.128 / 32 FMA
#define TPOS 68   // padded stride for transposed tiles (float4-aligned, low conflict)

__global__ void __launch_bounds__(256) attn_kernel(const float* __restrict__ Q,
                                                   const float* __restrict__ Km,
                                                   const float* __restrict__ Vm,
                                                   float* __restrict__ O) {
    const int b = blockIdx.z;
    const int h = blockIdx.y;
    const int q0 = blockIdx.x * 64;

    extern __shared__ float sm[];
    float* qs_t = sm;                        // [128][TPOS]  (Q^T: [d][q])
    float* ks_t = qs_t + 128 * TPOS;         // [128][TPOS]  (K^T: [d][k])
    float* vs   = ks_t + 128 * TPOS;         // [64][128]    (V row-major)
    float* ss   = vs + 64 * 128;             // [64][TPOS]   (scores [q][k])
    float* m_s  = ss + 64 * TPOS;            // [64]
    float* l_s  = m_s + 64;                  // [64]
    float* f_s  = l_s + 64;                  // [64]

    const int tid = threadIdx.x;
    const int tx = tid & 15;
    const int ty = tid >> 4;
    const int wid = tid >> 5;
    const int lane = tid & 31;
    const float inv_norm = 0.08838834764831845f;  // 1/sqrt(128)

    // load Q tile transposed: scalar LDG (coalesced) + conflict-light STS
    {
        const float* qbase = Q + (size_t)(b * SEQ + q0) * HIDDEN + h * HEAD_DIM;
#pragma unroll
        for (int it = 0; it < 32; it++) {
            int i = tid + it * 256;
            int r = i >> 7;         // query row 0..63
            int c = i & 127;        // dim 0..127
            qs_t[c * TPOS + r] = qbase[(size_t)r * HIDDEN + c];
        }
    }
    if (tid < 64) {
        m_s[tid] = -3.0e38f;
        l_s[tid] = 0.0f;
    }
    __syncthreads();

    // PV accumulators: thread (ty,tx) owns queries ty*4..+3, dims tx*8..+7
    float accv[4][8];
#pragma unroll
    for (int i = 0; i < 4; i++)
#pragma unroll
        for (int j = 0; j < 8; j++) accv[i][j] = 0.0f;

    for (int t0 = 0; t0 < SEQ; t0 += 64) {
        // K tile transposed (scalar), V tile row-major (float4)
        {
            const float* kbase = Km + (size_t)(b * SEQ + t0) * HEAD_DIM;
#pragma unroll
            for (int it = 0; it < 32; it++) {
                int i = tid + it * 256;
                int r = i >> 7;
                int c = i & 127;
                ks_t[c * TPOS + r] = kbase[(size_t)r * HEAD_DIM + c];
            }
            const float* vbase = Vm + (size_t)(b * SEQ + t0) * HEAD_DIM;
#pragma unroll
            for (int it = 0; it < 8; it++) {
                int i = tid + it * 256;
                int r = i >> 5;
                int c4 = (i & 31) * 4;
                *(float4*)(vs + r * 128 + c4) = *(const float4*)(vbase + (size_t)r * HEAD_DIM + c4);
            }
        }
        __syncthreads();

        // ---- QK^T: 64x64 scores, 4x4 microtile, float4 LDS on both operands
        float s[4][4];
#pragma unroll
        for (int i = 0; i < 4; i++)
#pragma unroll
            for (int j = 0; j < 4; j++) s[i][j] = 0.0f;

#pragma unroll 4
        for (int kk = 0; kk < 128; kk++) {
            float4 a = *(const float4*)(qs_t + kk * TPOS + ty * 4);
            float4 bq = *(const float4*)(ks_t + kk * TPOS + tx * 4);
            s[0][0] = fmaf(a.x, bq.x, s[0][0]); s[0][1] = fmaf(a.x, bq.y, s[0][1]);
            s[0][2] = fmaf(a.x, bq.z, s[0][2]); s[0][3] = fmaf(a.x, bq.w, s[0][3]);
            s[1][0] = fmaf(a.y, bq.x, s[1][0]); s[1][1] = fmaf(a.y, bq.y, s[1][1]);
            s[1][2] = fmaf(a.y, bq.z, s[1][2]); s[1][3] = fmaf(a.y, bq.w, s[1][3]);
            s[2][0] = fmaf(a.z, bq.x, s[2][0]); s[2][1] = fmaf(a.z, bq.y, s[2][1]);
            s[2][2] = fmaf(a.z, bq.z, s[2][2]); s[2][3] = fmaf(a.z, bq.w, s[2][3]);
            s[3][0] = fmaf(a.w, bq.x, s[3][0]); s[3][1] = fmaf(a.w, bq.y, s[3][1]);
            s[3][2] = fmaf(a.w, bq.z, s[3][2]); s[3][3] = fmaf(a.w, bq.w, s[3][3]);
        }
#pragma unroll
        for (int i = 0; i < 4; i++) {
            float4 sv;
            sv.x = s[i][0] * inv_norm;
            sv.y = s[i][1] * inv_norm;
            sv.z = s[i][2] * inv_norm;
            sv.w = s[i][3] * inv_norm;
            *(float4*)(ss + (ty * 4 + i) * TPOS + tx * 4) = sv;
        }
        __syncthreads();

        // ---- online softmax: warp `wid` owns rows wid*8..+7
#pragma unroll
        for (int rr = 0; rr < 8; rr++) {
            int row = wid * 8 + rr;
            float v0 = ss[row * TPOS + lane];
            float v1 = ss[row * TPOS + 32 + lane];
            float mx = fmaxf(v0, v1);
#pragma unroll
            for (int off = 16; off > 0; off >>= 1)
                mx = fmaxf(mx, __shfl_xor_sync(0xffffffffu, mx, off));
            float m_old = m_s[row];
            float m_new = fmaxf(m_old, mx);
            float p0 = __expf(v0 - m_new);
            float p1 = __expf(v1 - m_new);
            ss[row * TPOS + lane] = p0;
            ss[row * TPOS + 32 + lane] = p1;
            float sum = p0 + p1;
#pragma unroll
            for (int off = 16; off > 0; off >>= 1)
                sum += __shfl_xor_sync(0xffffffffu, sum, off);
            if (lane == 0) {
                float f = __expf(m_old - m_new);
                l_s[row] = l_s[row] * f + sum;
                m_s[row] = m_new;
                f_s[row] = f;
            }
        }
        __syncthreads();

        // ---- rescale + P @ V: 4x8 microtile
        {
            float f0 = f_s[ty * 4 + 0];
            float f1 = f_s[ty * 4 + 1];
            float f2 = f_s[ty * 4 + 2];
            float f3 = f_s[ty * 4 + 3];
#pragma unroll
            for (int j = 0; j < 8; j++) {
                accv[0][j] *= f0;
                accv[1][j] *= f1;
                accv[2][j] *= f2;
                accv[3][j] *= f3;
            }
        }
#pragma unroll 4
        for (int kk = 0; kk < 64; kk++) {
            float p0 = ss[(ty * 4 + 0) * TPOS + kk];
            float p1 = ss[(ty * 4 + 1) * TPOS + kk];
            float p2 = ss[(ty * 4 + 2) * TPOS + kk];
            float p3 = ss[(ty * 4 + 3) * TPOS + kk];
            float4 v0 = *(const float4*)(vs + kk * 128 + tx * 8);
            float4 v1 = *(const float4*)(vs + kk * 128 + tx * 8 + 4);
            accv[0][0] = fmaf(p0, v0.x, accv[0][0]); accv[0][1] = fmaf(p0, v0.y, accv[0][1]);
            accv[0][2] = fmaf(p0, v0.z, accv[0][2]); accv[0][3] = fmaf(p0, v0.w, accv[0][3]);
            accv[0][4] = fmaf(p0, v1.x, accv[0][4]); accv[0][5] = fmaf(p0, v1.y, accv[0][5]);
            accv[0][6] = fmaf(p0, v1.z, accv[0][6]); accv[0][7] = fmaf(p0, v1.w, accv[0][7]);
            accv[1][0] = fmaf(p1, v0.x, accv[1][0]); accv[1][1] = fmaf(p1, v0.y, accv[1][1]);
            accv[1][2] = fmaf(p1, v0.z, accv[1][2]); accv[1][3] = fmaf(p1, v0.w, accv[1][3]);
            accv[1][4] = fmaf(p1, v1.x, accv[1][4]); accv[1][5] = fmaf(p1, v1.y, accv[1][5]);
            accv[1][6] = fmaf(p1, v1.z, accv[1][6]); accv[1][7] = fmaf(p1, v1.w, accv[1][7]);
            accv[2][0] = fmaf(p2, v0.x, accv[2][0]); accv[2][1] = fmaf(p2, v0.y, accv[2][1]);
            accv[2][2] = fmaf(p2, v0.z, accv[2][2]); accv[2][3] = fmaf(p2, v0.w, accv[2][3]);
            accv[2][4] = fmaf(p2, v1.x, accv[2][4]); accv[2][5] = fmaf(p2, v1.y, accv[2][5]);
            accv[2][6] = fmaf(p2, v1.z, accv[2][6]); accv[2][7] = fmaf(p2, v1.w, accv[2][7]);
            accv[3][0] = fmaf(p3, v0.x, accv[3][0]); accv[3][1] = fmaf(p3, v0.y, accv[3][1]);
            accv[3][2] = fmaf(p3, v0.z, accv[3][2]); accv[3][3] = fmaf(p3, v0.w, accv[3][3]);
            accv[3][4] = fmaf(p3, v1.x, accv[3][4]); accv[3][5] = fmaf(p3, v1.y, accv[3][5]);
            accv[3][6] = fmaf(p3, v1.z, accv[3][6]); accv[3][7] = fmaf(p3, v1.w, accv[3][7]);
        }
        __syncthreads();
    }

    // ---- epilogue
#pragma unroll
    for (int i = 0; i < 4; i++) {
        float linv = 1.0f / l_s[ty * 4 + i];
        float* optr = O + (size_t)(b * SEQ + q0 + ty * 4 + i) * HIDDEN + h * HEAD_DIM + tx * 8;
        float4 o0, o1;
        o0.x = accv[i][0] * linv; o0.y = accv[i][1] * linv;
        o0.z = accv[i][2] * linv; o0.w = accv[i][3] * linv;
        o1.x = accv[i][4] * linv; o1.y = accv[i][5] * linv;
        o1.z = accv[i][6] * linv; o1.w = accv[i][7] * linv;
        *(float4*)optr = o0;
        *(float4*)(optr + 4) = o1;
    }
}

// ---------------- launch ----------------
extern "C" void kernel_launch(void* const* d_in, const int* in_sizes, int n_in,
                              void* d_out, int out_size) {
    (void)in_sizes; (void)n_in; (void)out_size;
    const float* x  = (const float*)d_in[0];
    const float* wq = (const float*)d_in[1];
    const float* wk = (const float*)d_in[2];
    const float* wv = (const float*)d_in[3];
    const float* wo = (const float*)d_in[4];
    float* out = (float*)d_out;

    float *qb, *kb, *vb, *ab;
    cudaGetSymbolAddress((void**)&qb, g_q);
    cudaGetSymbolAddress((void**)&kb, g_k);
    cudaGetSymbolAddress((void**)&vb, g_v);
    cudaGetSymbolAddress((void**)&ab, g_att);

    const int smem_attn = (128 * TPOS + 128 * TPOS + 64 * 128 + 64 * TPOS + 3 * 64)
                          * (int)sizeof(float);
    static int configured = 0;
    if (!configured) {
        cudaFuncSetAttribute(attn_kernel, cudaFuncAttributeMaxDynamicSharedMemorySize,
                             smem_attn);
        configured = 1;
    }

    dim3 blk(256);
    gemm_abt<<<dim3(HIDDEN / 128, MROWS / 128), blk>>>(x, wq, qb, MROWS, HIDDEN, HIDDEN);
    gemm_abt<<<dim3(HEAD_DIM / 128, MROWS / 128), blk>>>(x, wk, kb, MROWS, HEAD_DIM, HIDDEN);
    gemm_abt<<<dim3(HEAD_DIM / 128, MROWS / 128), blk>>>(x, wv, vb, MROWS, HEAD_DIM, HIDDEN);
    attn_kernel<<<dim3(SEQ / 64, HEADS, BATCH), blk, smem_attn>>>(qb, kb, vb, ab);
    gemm_abt<<<dim3(HIDDEN / 128, MROWS / 128), blk>>>(ab, wo, out, MROWS, HIDDEN, HIDDEN);
}